// round 13
// baseline (speedup 1.0000x reference)
#include <cuda_runtime.h>
#include <cuda_fp16.h>
#include <math_constants.h>
#include <cstdint>

#define NB 4
#define NC 1024
#define NT 1024
#define NH 16
#define NDH 64
#define KDIM 1024

// ---------------------------------------------------------------------------
// Scratch (__device__ globals; allocation-free)
// ---------------------------------------------------------------------------
// Weights fp16: [q(1M) | kv(2M) | o(1M)] elems
__device__ __align__(16) __half g_w_hi[4 * 1024 * 1024];
// Activations fp16, [T][C] rows: [x(4M) | c(4M) | att(4M)] elems
__device__ __align__(16) __half g_a_h[12 * 1024 * 1024];
// RoPE'd q/k/v fp16, [b][h][t][64] rows: [q(4M) | k(4M) | v(4M)]
// (q pre-scaled by 1/8 = softmax scale; exact power of two)
__device__ __align__(16) __half g_qkvh[12 * 1024 * 1024];

#define QOFF ((size_t)0)
#define KOFF ((size_t)4 * 1024 * 1024)
#define VOFF ((size_t)8 * 1024 * 1024)
#define XOFF ((size_t)0)
#define COFF ((size_t)4 * 1024 * 1024)
#define ATTOFF ((size_t)8 * 1024 * 1024)

// ---------------------------------------------------------------------------
// Base-ISA tensor helpers (sm_80+ features; compile for plain sm_100)
// ---------------------------------------------------------------------------
__device__ __forceinline__ uint32_t smem_to_u32(const void* p) {
    uint32_t a;
    asm("{ .reg .u64 t; cvta.to.shared.u64 t, %1; cvt.u32.u64 %0, t; }"
        : "=r"(a) : "l"(p));
    return a;
}
#define CP_ASYNC16(dst, src) \
    asm volatile("cp.async.cg.shared.global [%0], [%1], 16;" \
        :: "r"(dst), "l"(src) : "memory")
#define CP_COMMIT() asm volatile("cp.async.commit_group;" ::: "memory")
#define CP_WAIT(n)  asm volatile("cp.async.wait_group %0;" :: "n"(n) : "memory")
#define LDMX4(r, addr) \
    asm volatile("ldmatrix.sync.aligned.m8n8.x4.shared.b16 {%0,%1,%2,%3}, [%4];" \
        : "=r"((r)[0]), "=r"((r)[1]), "=r"((r)[2]), "=r"((r)[3]) : "r"(addr))
#define LDMX4T(r, addr) \
    asm volatile("ldmatrix.sync.aligned.m8n8.x4.trans.shared.b16 {%0,%1,%2,%3}, [%4];" \
        : "=r"((r)[0]), "=r"((r)[1]), "=r"((r)[2]), "=r"((r)[3]) : "r"(addr))

__device__ __forceinline__ void mma_f16(float* c, const uint32_t* a,
                                        const uint32_t* b) {
    asm volatile(
        "mma.sync.aligned.m16n8k16.row.col.f32.f16.f16.f32 "
        "{%0,%1,%2,%3}, {%4,%5,%6,%7}, {%8,%9}, {%0,%1,%2,%3};"
        : "+f"(c[0]), "+f"(c[1]), "+f"(c[2]), "+f"(c[3])
        : "r"(a[0]), "r"(a[1]), "r"(a[2]), "r"(a[3]), "r"(b[0]), "r"(b[1]));
}

__device__ __forceinline__ uint32_t pack2h(float a, float b) {
    __half2 h = __halves2half2(__float2half(a), __float2half(b));
    return *(uint32_t*)&h;
}

// Guaranteed-MUFU exp2 (avoids exp2f's precise path without fast-math)
__device__ __forceinline__ float ex2(float x) {
    float r;
    asm("ex2.approx.f32 %0, %1;" : "=f"(r) : "f"(x));
    return r;
}

// ---------------------------------------------------------------------------
// Weight convert (all three in one launch): fp32 -> fp16
// ---------------------------------------------------------------------------
__global__ __launch_bounds__(256) void conv_w_kernel(
    const float* __restrict__ qw, const float* __restrict__ kvw,
    const float* __restrict__ ow)
{
    const int stride = gridDim.x * blockDim.x;
    const int M1 = 1024 * 1024, M3 = 3 * 1024 * 1024, M4 = 4 * 1024 * 1024;
    for (int i = blockIdx.x * blockDim.x + threadIdx.x; i < M4; i += stride) {
        float v;
        if (i < M1)      v = qw[i];
        else if (i < M3) v = kvw[i - M1];
        else             v = ow[i - M3];
        g_w_hi[i] = __float2half(v);
    }
}

// ---------------------------------------------------------------------------
// Fused activation transpose: x,c [C][T] fp32 -> [T][C] fp16, half2 stores.
// Tile 64c x 32t. Grid (32, 16, 8): z<4 -> x batch z; else c batch z-4.
// ---------------------------------------------------------------------------
__global__ __launch_bounds__(256) void tsplit2_kernel(
    const float* __restrict__ x, const float* __restrict__ c)
{
    __shared__ float tile[64][33];
    const int z = blockIdx.z;
    const float* src = (z < 4) ? x + (size_t)z * NC * NT
                               : c + (size_t)(z - 4) * NC * NT;
    const size_t db = (z < 4) ? XOFF + (size_t)z * NC * NT
                              : COFF + (size_t)(z - 4) * NC * NT;
    const int t0 = blockIdx.x * 32, c0 = blockIdx.y * 64;
    const int tx = threadIdx.x, ty = threadIdx.y;
#pragma unroll
    for (int i = 0; i < 8; i++)
        tile[ty + 8 * i][tx] = src[(size_t)(c0 + ty + 8 * i) * NT + t0 + tx];
    __syncthreads();
#pragma unroll
    for (int i = 0; i < 4; i++) {
        const int t = t0 + ty + 8 * i;
        __half2 h = __halves2half2(__float2half(tile[2 * tx][ty + 8 * i]),
                                   __float2half(tile[2 * tx + 1][ty + 8 * i]));
        *(__half2*)&g_a_h[db + (size_t)t * NC + c0 + 2 * tx] = h;
    }
}

// ---------------------------------------------------------------------------
// fp16 GEMM mainloop: acc = W[m0..][.] * X[n0..][.]^T
// 128x128 CTA tile, 8 warps, K-chunk 64, cp.async 3-stage pipeline.
// B loaded in n16 pairs via ldmatrix.x4.
// ---------------------------------------------------------------------------
#define BUF_BYTES 32768u
#define OFF_B 16384u
#define SMEM_GEMM (3 * 32768)

__device__ __forceinline__ void gemm_mainloop(
    const __half* __restrict__ Wh, const __half* __restrict__ Xh,
    char* sm, int m0, int n0, float acc[4][4][4])
{
    const uint32_t smb = smem_to_u32(sm);
    const int tid = threadIdx.x;
    const int wid = tid >> 5, lane = tid & 31;
    const int wm = (wid >> 2) * 64;
    const int wn = (wid & 3) * 32;

#pragma unroll
    for (int mt = 0; mt < 4; mt++)
#pragma unroll
        for (int nt = 0; nt < 4; nt++)
#pragma unroll
            for (int i = 0; i < 4; i++) acc[mt][nt][i] = 0.f;

    auto stage = [&](int ch, int buf) {
        const uint32_t base = smb + buf * BUF_BYTES;
        const int k0 = ch * 64;
#pragma unroll
        for (int it = 0; it < 4; it++) {
            const int idx = tid + it * 256;
            const int row = idx >> 3, v = idx & 7;
            const uint32_t dst = base + row * 128 + ((v * 16) ^ ((row & 7) << 4));
            CP_ASYNC16(dst,         Wh + (size_t)(m0 + row) * KDIM + k0 + v * 8);
            CP_ASYNC16(dst + OFF_B, Xh + (size_t)(n0 + row) * KDIM + k0 + v * 8);
        }
        CP_COMMIT();
    };

    stage(0, 0);
    stage(1, 1);

    const int a_row_in = (lane & 7) + ((lane >> 3) & 1) * 8;
    const int a_colsel = (lane >> 4) & 1;
    const int b_row_in = (lane & 7) + ((lane >> 4) << 3);
    const int b_colsel = (lane >> 3) & 1;

    int buf = 0;
    for (int ch = 0; ch < 16; ch++) {
        if (ch < 14) {
            int nb = buf + 2; if (nb >= 3) nb -= 3;
            stage(ch + 2, nb);
            CP_WAIT(2);
        } else if (ch == 14) {
            CP_WAIT(1);
        } else {
            CP_WAIT(0);
        }
        __syncthreads();
        const uint32_t base = smb + buf * BUF_BYTES;

#pragma unroll
        for (int ks = 0; ks < 4; ks++) {
            uint32_t ah[4][4];
#pragma unroll
            for (int mt = 0; mt < 4; mt++) {
                const int r = wm + mt * 16 + a_row_in;
                const uint32_t col = (uint32_t)(ks * 32 + a_colsel * 16);
                LDMX4(ah[mt], base + r * 128 + (col ^ ((r & 7) << 4)));
            }
            uint32_t bh[2][4];
#pragma unroll
            for (int ntp = 0; ntp < 2; ntp++) {
                const int r = wn + ntp * 16 + b_row_in;
                const uint32_t col = (uint32_t)(ks * 32 + b_colsel * 16);
                LDMX4(bh[ntp], base + OFF_B + r * 128 + (col ^ ((r & 7) << 4)));
            }
#pragma unroll
            for (int mt = 0; mt < 4; mt++)
#pragma unroll
                for (int nt = 0; nt < 4; nt++)
                    mma_f16(acc[mt][nt], ah[mt], bh[nt >> 1] + (nt & 1) * 2);
        }
        __syncthreads();
        if (++buf == 3) buf = 0;
    }
}

// ---------------------------------------------------------------------------
// Fused q+kv projection with RoPE + fp16 epilogue writing [b][h][t][64].
// Grid (8, 24, NB): yb<8 -> q (x input); yb>=8 -> kv (c input).
// Q additionally pre-scaled by 1/8 (softmax scale; exact pow2).
// ---------------------------------------------------------------------------
__global__ __launch_bounds__(256) void qkv_gemm_kernel(
    const float* __restrict__ q_b, const float* __restrict__ kv_b)
{
    extern __shared__ char sm[];
    const int b = blockIdx.z, yb = blockIdx.y;
    const int n0 = blockIdx.x * 128;
    const bool isQ = (yb < 8);
    const int m0 = isQ ? yb * 128 : (yb - 8) * 128;
    const __half* W = isQ ? g_w_hi : g_w_hi + 1024 * 1024;
    const __half* X = g_a_h + (isQ ? XOFF : COFF) + (size_t)b * NC * NT;
    const float* bias = isQ ? q_b : kv_b;

    float acc[4][4][4];
    gemm_mainloop(W, X, sm, m0, n0, acc);

    const int tid = threadIdx.x, wid = tid >> 5, lane = tid & 31;
    const int wm = (wid >> 2) * 64, wn = (wid & 3) * 32;
    const bool isV = (!isQ) && (m0 >= 1024);

    // bias (before RoPE, matching reference)
#pragma unroll
    for (int mt = 0; mt < 4; mt++) {
        const int r0 = wm + mt * 16 + (lane >> 2);
        const float b0 = bias[m0 + r0], b1 = bias[m0 + r0 + 8];
#pragma unroll
        for (int nt = 0; nt < 4; nt++) {
            acc[mt][nt][0] += b0; acc[mt][nt][1] += b0;
            acc[mt][nt][2] += b1; acc[mt][nt][3] += b1;
        }
    }

    // RoPE on head dims [0,32): pair (j, j+16) = (acc[0], acc[1]) same thread
    if (!isV) {
        const float LN = 0.57564627324851145f;  // ln(10000)/16
        const int j0 = lane >> 2;
        const float th0 = __expf(-(float)j0 * LN);
        const float th1 = __expf(-(float)(j0 + 8) * LN);
#pragma unroll
        for (int nt = 0; nt < 4; nt++) {
#pragma unroll
            for (int i = 0; i < 4; i++) {
                const int t = n0 + wn + nt * 8 + (lane & 3) * 2 + (i & 1);
                const float th = (i >= 2) ? th1 : th0;
                float sn, cs;
                sincosf((float)t * th, &sn, &cs);
                const float a0 = acc[0][nt][i], a1 = acc[1][nt][i];
                acc[0][nt][i] = a0 * cs - a1 * sn;
                acc[1][nt][i] = a1 * cs + a0 * sn;
            }
        }
    }

    // Q pre-scale by softmax scale 1/8 (exact)
    const float qscale = isQ ? 0.125f : 1.0f;

    // stage [t][c] (pad 136) in smem as fp16
    __syncthreads();
    __half* s_hi = (__half*)sm;
#pragma unroll
    for (int mt = 0; mt < 4; mt++) {
#pragma unroll
        for (int nt = 0; nt < 4; nt++) {
#pragma unroll
            for (int i = 0; i < 4; i++) {
                const int r = wm + mt * 16 + (lane >> 2) + ((i >> 1) << 3);
                const int col = wn + nt * 8 + (lane & 3) * 2 + (i & 1);
                s_hi[col * 136 + r] = __float2half(acc[mt][nt][i] * qscale);
            }
        }
    }
    __syncthreads();

    // coalesced copy-out: 128 t x 128 c (2 heads x 64)
    const size_t roff = isQ ? QOFF : (m0 < 1024 ? KOFF : VOFF);
    const int hd0 = (m0 & 1023) >> 6;
    const int z0 = b * NH + hd0;
    for (int idx = tid; idx < 128 * 16; idx += 256) {
        const int t = idx >> 4, u = idx & 15;
        const int cc = u * 8;
        const int hd = cc >> 6, cl = cc & 63;
        const size_t go = ((size_t)(z0 + hd) * NT + (n0 + t)) * 64 + cl;
        *(uint4*)(g_qkvh + roff + go) = *(uint4*)(s_hi + t * 136 + cc);
    }
}

// ---------------------------------------------------------------------------
// Output projection: out = o_w @ att + o_b (fp32 out)
// ---------------------------------------------------------------------------
__global__ __launch_bounds__(256) void o_gemm_kernel(
    const float* __restrict__ o_b, float* __restrict__ out)
{
    extern __shared__ char sm[];
    const int b = blockIdx.z;
    const int m0 = blockIdx.y * 128, n0 = blockIdx.x * 128;

    float acc[4][4][4];
    gemm_mainloop(g_w_hi + 3 * 1024 * 1024,
                  g_a_h + ATTOFF + (size_t)b * NC * NT, sm, m0, n0, acc);

    const int tid = threadIdx.x, wid = tid >> 5, lane = tid & 31;
    const int wm = (wid >> 2) * 64, wn = (wid & 3) * 32;
    float* Yb = out + (size_t)b * NC * NT;

#pragma unroll
    for (int mt = 0; mt < 4; mt++) {
        const int r0 = m0 + wm + mt * 16 + (lane >> 2);
        const float bv0 = o_b[r0], bv1 = o_b[r0 + 8];
#pragma unroll
        for (int nt = 0; nt < 4; nt++) {
            const int cn = n0 + wn + nt * 8 + (lane & 3) * 2;
            *(float2*)&Yb[(size_t)r0 * NT + cn] =
                make_float2(acc[mt][nt][0] + bv0, acc[mt][nt][1] + bv0);
            *(float2*)&Yb[(size_t)(r0 + 8) * NT + cn] =
                make_float2(acc[mt][nt][2] + bv1, acc[mt][nt][3] + bv1);
        }
    }
}

// ---------------------------------------------------------------------------
// Register-resident FA2 attention, fp16. Q pre-scaled by 1/8.
// Grid (T/128, NH, NB), 256 threads (8 warps), 16 query rows/warp.
// K and V loaded in n16 pairs via ldmatrix.x4(.trans). ex2.approx softmax.
// SMEM: Q staged in first 16KB, then 2 x 16KB KV buffers (K 8KB | V 8KB).
// ---------------------------------------------------------------------------
#define KV_BUF 16384u
#define SMEM_ATT 32768
#define LOG2E 1.4426950408889634f

__global__ __launch_bounds__(256) void attn_mma_kernel()
{
    extern __shared__ char sm[];
    const uint32_t smb = smem_to_u32(sm);
    const int tid = threadIdx.x, wid = tid >> 5, lane = tid & 31;
    const int b = blockIdx.z, h = blockIdx.y;
    const int q0 = blockIdx.x * 128;
    const int z = b * NH + h;
    const int wm = wid * 16;

    // ---- stage Q (16KB), load frags, free smem ----
    {
        const __half* qhp = g_qkvh + QOFF + ((size_t)z * NT + q0) * 64;
        for (int idx = tid; idx < 1024; idx += 256) {
            const int row = idx >> 3, v = idx & 7;
            const uint32_t d = row * 128 + ((v * 16) ^ ((row & 7) << 4));
            *(uint4*)(sm + d) = *((const uint4*)(qhp + row * 64) + v);
        }
    }
    __syncthreads();

    const int a_row = (lane & 7) + ((lane >> 3) & 1) * 8;
    const int a_cs  = (lane >> 4) & 1;
    uint32_t qh[4][4];
#pragma unroll
    for (int ks = 0; ks < 4; ks++) {
        const int r = wm + a_row;
        LDMX4(qh[ks],
              smb + r * 128 + ((uint32_t)(ks * 32 + a_cs * 16) ^ ((r & 7) << 4)));
    }
    __syncthreads();   // all warps done reading Q staging

    // ---- KV staging ----
    const __half* kh_g = g_qkvh + KOFF + (size_t)z * NT * 64;
    const __half* vh_g = g_qkvh + VOFF + (size_t)z * NT * 64;

    auto stageKV = [&](int ch, int buf) {
        const uint32_t base = smb + buf * KV_BUF;
        const int k0 = ch * 64;
#pragma unroll
        for (int it = 0; it < 2; it++) {
            const int idx = tid + it * 256;       // 0..511
            const int row = idx >> 3, v = idx & 7;
            const uint32_t d = row * 128 + ((v * 16) ^ ((row & 7) << 4));
            const size_t go = (size_t)(k0 + row) * 64 + v * 8;
            CP_ASYNC16(base + d,        kh_g + go);
            CP_ASYNC16(base + 8192 + d, vh_g + go);
        }
        CP_COMMIT();
    };
    stageKV(0, 0);

    float m0 = -CUDART_INF_F, m1 = -CUDART_INF_F;
    float l0 = 0.f, l1 = 0.f;
    float oacc[8][4];
#pragma unroll
    for (int nt = 0; nt < 8; nt++)
#pragma unroll
        for (int i = 0; i < 4; i++) oacc[nt][i] = 0.f;

    // x4 pair-load lane mappings
    const int bk_row = (lane & 7) + ((lane >> 4) << 3);   // K: n-row within pair
    const int bk_cs  = (lane >> 3) & 1;                   // K: k-half
    const int vk_row = (lane & 7) + ((lane >> 3) & 1) * 8; // V: k-row within 16
    const int v_cs   = (lane >> 4) & 1;                   // V: n-half (16B)

    for (int ch = 0; ch < 16; ch++) {
        if (ch < 15) { stageKV(ch + 1, (ch + 1) & 1); CP_WAIT(1); }
        else         { CP_WAIT(0); }
        __syncthreads();
        const uint32_t base = smb + (ch & 1) * KV_BUF;

        // ---- S = Q K^T (K in n16 pairs) ----
        float sacc[8][4];
#pragma unroll
        for (int nt = 0; nt < 8; nt++)
#pragma unroll
            for (int i = 0; i < 4; i++) sacc[nt][i] = 0.f;

#pragma unroll
        for (int ks = 0; ks < 4; ks++) {
#pragma unroll
            for (int ntp = 0; ntp < 4; ntp++) {
                uint32_t bb[4];
                const int r = ntp * 16 + bk_row;
                LDMX4(bb, base + r * 128 +
                          ((uint32_t)(ks * 32 + bk_cs * 16) ^ ((r & 7) << 4)));
                mma_f16(sacc[2 * ntp],     qh[ks], bb);
                mma_f16(sacc[2 * ntp + 1], qh[ks], bb + 2);
            }
        }

        // ---- in-register online softmax (ex2.approx; scores pre-scaled) ----
        float mx0 = -CUDART_INF_F, mx1 = -CUDART_INF_F;
#pragma unroll
        for (int nt = 0; nt < 8; nt++) {
            mx0 = fmaxf(mx0, fmaxf(sacc[nt][0], sacc[nt][1]));
            mx1 = fmaxf(mx1, fmaxf(sacc[nt][2], sacc[nt][3]));
        }
        mx0 = fmaxf(mx0, __shfl_xor_sync(0xffffffffu, mx0, 1));
        mx0 = fmaxf(mx0, __shfl_xor_sync(0xffffffffu, mx0, 2));
        mx1 = fmaxf(mx1, __shfl_xor_sync(0xffffffffu, mx1, 1));
        mx1 = fmaxf(mx1, __shfl_xor_sync(0xffffffffu, mx1, 2));
        const float mn0 = fmaxf(m0, mx0), mn1 = fmaxf(m1, mx1);
        const float al0 = ex2((m0 - mn0) * LOG2E);
        const float al1 = ex2((m1 - mn1) * LOG2E);
        m0 = mn0; m1 = mn1;
        const float c0 = mn0 * LOG2E, c1 = mn1 * LOG2E;
        float ls0 = 0.f, ls1 = 0.f;
#pragma unroll
        for (int nt = 0; nt < 8; nt++) {
            sacc[nt][0] = ex2(fmaf(sacc[nt][0], LOG2E, -c0));
            sacc[nt][1] = ex2(fmaf(sacc[nt][1], LOG2E, -c0));
            sacc[nt][2] = ex2(fmaf(sacc[nt][2], LOG2E, -c1));
            sacc[nt][3] = ex2(fmaf(sacc[nt][3], LOG2E, -c1));
            ls0 += sacc[nt][0] + sacc[nt][1];
            ls1 += sacc[nt][2] + sacc[nt][3];
        }
        ls0 += __shfl_xor_sync(0xffffffffu, ls0, 1);
        ls0 += __shfl_xor_sync(0xffffffffu, ls0, 2);
        ls1 += __shfl_xor_sync(0xffffffffu, ls1, 1);
        ls1 += __shfl_xor_sync(0xffffffffu, ls1, 2);
        l0 = l0 * al0 + ls0;
        l1 = l1 * al1 + ls1;
#pragma unroll
        for (int nt = 0; nt < 8; nt++) {
            oacc[nt][0] *= al0; oacc[nt][1] *= al0;
            oacc[nt][2] *= al1; oacc[nt][3] *= al1;
        }

        // ---- O += P V (P packed in regs; V in n16 pairs via x4.trans) ----
#pragma unroll
        for (int ksp = 0; ksp < 4; ksp++) {
            uint32_t ph[4];
            ph[0] = pack2h(sacc[2 * ksp][0],     sacc[2 * ksp][1]);
            ph[1] = pack2h(sacc[2 * ksp][2],     sacc[2 * ksp][3]);
            ph[2] = pack2h(sacc[2 * ksp + 1][0], sacc[2 * ksp + 1][1]);
            ph[3] = pack2h(sacc[2 * ksp + 1][2], sacc[2 * ksp + 1][3]);
            const int k = ksp * 16 + vk_row;
#pragma unroll
            for (int ntp = 0; ntp < 4; ntp++) {
                uint32_t vv[4];
                const uint32_t col = (uint32_t)(ntp * 32 + v_cs * 16);
                LDMX4T(vv, base + 8192 + k * 128 + (col ^ ((k & 7) << 4)));
                mma_f16(oacc[2 * ntp],     ph, vv);
                mma_f16(oacc[2 * ntp + 1], ph, vv + 2);
            }
        }
        __syncthreads();   // compute done before next stage overwrites
    }

    // ---- epilogue: normalize, write fp16 to att region ----
    const float il0 = 1.f / l0, il1 = 1.f / l1;
    const int r = wm + (lane >> 2);
    const size_t rowo = ATTOFF + (size_t)b * (NC * NT) +
                        (size_t)(q0 + r) * NC + h * 64;
#pragma unroll
    for (int nt = 0; nt < 8; nt++) {
        const int d = nt * 8 + (lane & 3) * 2;
        *(__half2*)(g_a_h + rowo + d) = __halves2half2(
            __float2half(oacc[nt][0] * il0), __float2half(oacc[nt][1] * il0));
        *(__half2*)(g_a_h + rowo + 8 * NC + d) = __halves2half2(
            __float2half(oacc[nt][2] * il1), __float2half(oacc[nt][3] * il1));
    }
}

// ---------------------------------------------------------------------------
extern "C" void kernel_launch(void* const* d_in, const int* in_sizes, int n_in,
                              void* d_out, int out_size)
{
    const float* x    = (const float*)d_in[0];
    const float* c    = (const float*)d_in[1];
    const float* q_w  = (const float*)d_in[2];
    const float* q_b  = (const float*)d_in[3];
    const float* kv_w = (const float*)d_in[4];
    const float* kv_b = (const float*)d_in[5];
    const float* o_w  = (const float*)d_in[6];
    const float* o_b  = (const float*)d_in[7];
    float* out = (float*)d_out;

    static bool attr_done = false;
    if (!attr_done) {
        cudaFuncSetAttribute(qkv_gemm_kernel, cudaFuncAttributeMaxDynamicSharedMemorySize, SMEM_GEMM);
        cudaFuncSetAttribute(o_gemm_kernel, cudaFuncAttributeMaxDynamicSharedMemorySize, SMEM_GEMM);
        cudaFuncSetAttribute(attn_mma_kernel, cudaFuncAttributeMaxDynamicSharedMemorySize, SMEM_ATT);
        attr_done = true;
    }

    // Convert all weights to fp16 (one launch)
    conv_w_kernel<<<1024, 256>>>(q_w, kv_w, o_w);
    // Fused transpose of x and c to [T][C] fp16
    tsplit2_kernel<<<dim3(32, 16, 2 * NB), dim3(32, 8)>>>(x, c);
    // Fused q+kv projection with RoPE epilogue (Q pre-scaled by 1/8)
    qkv_gemm_kernel<<<dim3(8, 24, NB), 256, SMEM_GEMM>>>(q_b, kv_b);
    // register-resident FA2 attention (writes fp16 att activations)
    attn_mma_kernel<<<dim3(NT / 128, NH, NB), 256, SMEM_ATT>>>();
    // out = o_w @ att + o_b
    o_gemm_kernel<<<dim3(8, 8, NB), 256, SMEM_GEMM>>>(o_b, out);
}